// round 15
// baseline (speedup 1.0000x reference)
#include <cuda_runtime.h>
#include <cuda_bf16.h>
#include <math.h>
#include <stdint.h>

// Problem constants
#define NN 13
#define BB 2
#define TT 2048
#define DD 1024
#define ROW_F4 (DD / 4)          // 256 float4 per row
#define NTILES (BB * TT)         // 4096
#define CWARPS 16                // compute warps
#define CTHREADS 512             // compute threads
#define THREADS 544              // + 1 producer warp
#define GRID 152                 // 1 CTA per SM
#define SLOTS 4                  // power of two -> parity is bit-math
#define EPS 1.1920928955078125e-07f   // FLT_EPSILON

#define BUF_F4      (NN * ROW_F4)
#define TILE_BYTES  (BUF_F4 * 16)            // 53248
#define SMEM_BYTES  (SLOTS * TILE_BYTES)     // 212992

__device__ __forceinline__ uint32_t smem_u32(const void* p) {
    uint32_t a;
    asm("{ .reg .u64 t; cvta.to.shared.u64 t, %1; cvt.u32.u64 %0, t; }"
        : "=r"(a) : "l"(p));
    return a;
}
__device__ __forceinline__ void mbar_init(uint32_t m, uint32_t cnt) {
    asm volatile("mbarrier.init.shared.b64 [%0], %1;" :: "r"(m), "r"(cnt) : "memory");
}
__device__ __forceinline__ void mbar_expect_tx(uint32_t m, uint32_t bytes) {
    asm volatile("mbarrier.arrive.expect_tx.shared.b64 _, [%0], %1;"
                 :: "r"(m), "r"(bytes) : "memory");
}
__device__ __forceinline__ void mbar_arrive(uint32_t m) {
    asm volatile("mbarrier.arrive.shared.b64 _, [%0];" :: "r"(m) : "memory");
}
__device__ __forceinline__ void mbar_wait(uint32_t m, uint32_t parity) {
    asm volatile(
        "{\n\t.reg .pred P;\n\t"
        "WAIT_%=:\n\t"
        "mbarrier.try_wait.parity.acquire.cta.shared::cta.b64 P, [%0], %1, 0x989680;\n\t"
        "@P bra DONE_%=;\n\t"
        "bra WAIT_%=;\n\t"
        "DONE_%=:\n\t}"
        :: "r"(m), "r"(parity) : "memory");
}
__device__ __forceinline__ void tma_1d(uint32_t dst, const void* src,
                                       uint32_t bytes, uint32_t mbar) {
    asm volatile(
        "cp.async.bulk.shared::cta.global.mbarrier::complete_tx::bytes [%0], [%1], %2, [%3];"
        :: "r"(dst), "l"(src), "r"(bytes), "r"(mbar) : "memory");
}

__global__ __launch_bounds__(THREADS, 1)
void attn_res_block_kernel(const float4* __restrict__ V,
                           const float4* __restrict__ rms_w,
                           const float4* __restrict__ w_proj,
                           float4* __restrict__ out)
{
    extern __shared__ float4 sbuf[];                  // [SLOTS][NN][ROW_F4]
    __shared__ __align__(8) uint64_t mb_full[SLOTS];  // tx-count completion
    __shared__ __align__(8) uint64_t mb_empty[SLOTS]; // 16 consumer arrivals
    __shared__ float s_logit[SLOTS][NN];

    const int tid  = threadIdx.x;
    const int lane = tid & 31;
    const int wid  = tid >> 5;                        // 0..16

    const uint32_t full_a  = smem_u32(&mb_full[0]);
    const uint32_t empty_a = smem_u32(&mb_empty[0]);
    const uint32_t sb_a    = smem_u32(sbuf);

    if (tid == 0) {
        #pragma unroll
        for (int s = 0; s < SLOTS; s++) {
            mbar_init(full_a  + s * 8, 1);
            mbar_init(empty_a + s * 8, CWARPS);
        }
        asm volatile("fence.proxy.async.shared::cta;" ::: "memory");
    }
    __syncthreads();

    // ================= Producer warp (wid == 16) =================
    if (wid == CWARPS) {
        if (lane == 0) {
            int j = 0;
            for (int t = blockIdx.x; t < NTILES; t += GRID, j++) {
                const int s = j & (SLOTS - 1);
                const int u = j >> 2;                 // use-count of this slot
                if (u >= 1)                           // wait consumption #(u-1)
                    mbar_wait(empty_a + s * 8, (u - 1) & 1);
                mbar_expect_tx(full_a + s * 8, TILE_BYTES);
                #pragma unroll
                for (int n = 0; n < NN; n++)
                    tma_1d(sb_a + (uint32_t)(s * BUF_F4 + n * ROW_F4) * 16u,
                           (const void*)(V + ((long)n * NTILES + t) * ROW_F4),
                           (uint32_t)(ROW_F4 * 16), full_a + s * 8);
            }
        }
        return;
    }

    // ================= Consumer warps (tid < 512) =================
    // Lane-indexed combined weight (rms_weight * w_proj), registers.
    float4 cw[8];
    #pragma unroll
    for (int k = 0; k < 8; k++) {
        float4 a = rms_w[k * 32 + lane];
        float4 b = w_proj[k * 32 + lane];
        cw[k] = make_float4(a.x * b.x, a.y * b.y, a.z * b.z, a.w * b.w);
    }

    int j = 0;
    for (int tile = blockIdx.x; tile < NTILES; tile += GRID, j++) {
        const int s = j & (SLOTS - 1);
        mbar_wait(full_a + s * 8, (j >> 2) & 1);      // wait fill #(j>>2)

        const float4* cur = sbuf + s * BUF_F4;

        // ---- Phase 1 (row-mapped): warp w owns row w (w < 13).
        if (wid < NN) {
            float tss = 0.f, tdp = 0.f;
            #pragma unroll
            for (int k = 0; k < 8; k++) {
                float4 x = cur[wid * ROW_F4 + k * 32 + lane];
                tss = fmaf(x.x, x.x, fmaf(x.y, x.y, fmaf(x.z, x.z, fmaf(x.w, x.w, tss))));
                tdp = fmaf(x.x, cw[k].x, fmaf(x.y, cw[k].y, fmaf(x.z, cw[k].z, fmaf(x.w, cw[k].w, tdp))));
            }
            // Split-pair reduction: halve the shuffle chain.
            // After one xor-16 swap, lanes 0-15 reduce sum(ss), 16-31 sum(dp).
            float keep = (lane < 16) ? tss : tdp;
            float give = (lane < 16) ? tdp : tss;
            give = __shfl_xor_sync(0xFFFFFFFFu, give, 16);
            float r = keep + give;
            #pragma unroll
            for (int off = 8; off > 0; off >>= 1)
                r += __shfl_xor_sync(0xFFFFFFFFu, r, off);
            // lane 0 holds sum(ss); lane 16 holds sum(dp)
            float dp_tot = __shfl_sync(0xFFFFFFFFu, r, 16);
            if (lane == 0)
                s_logit[s][wid] = rsqrtf(r * (1.0f / DD) + EPS) * dp_tot;
        }
        // B1: compute warps only (named barrier; producer excluded).
        asm volatile("bar.sync 1, %0;" :: "n"(CTHREADS) : "memory");

        // ---- Softmax: per-warp redundant; values in lanes 0..12 -> 4 steps.
        float lv = (lane < NN) ? s_logit[s][lane] : -INFINITY;
        float mx = lv;
        #pragma unroll
        for (int off = 8; off > 0; off >>= 1)
            mx = fmaxf(mx, __shfl_xor_sync(0xFFFFFFFFu, mx, off));
        float e = (lane < NN) ? __expf(lv - mx) : 0.f;
        float sm = e;
        #pragma unroll
        for (int off = 8; off > 0; off >>= 1)
            sm += __shfl_xor_sync(0xFFFFFFFFu, sm, off);
        const float av = e * (1.0f / sm);             // alpha for depth = lane

        // Hoist alpha broadcasts (13 independent shuffles, pipelined).
        float a[NN];
        #pragma unroll
        for (int n = 0; n < NN; n++)
            a[n] = __shfl_sync(0xFFFFFFFFu, av, n);

        // ---- Phase 2 (column-mapped, float2 per thread over 512 threads).
        {
            const float2* cur2 = reinterpret_cast<const float2*>(cur);
            float2 o = make_float2(0.f, 0.f);
            #pragma unroll
            for (int n = 0; n < NN; n++) {
                float2 x = cur2[n * 512 + tid];
                o.x = fmaf(a[n], x.x, o.x);
                o.y = fmaf(a[n], x.y, o.y);
            }
            reinterpret_cast<float2*>(out)[(long)tile * 512 + tid] = o;
        }

        // Slot consumed by this warp (convergent) -> non-blocking arrive.
        if (lane == 0) mbar_arrive(empty_a + s * 8);
    }
}

extern "C" void kernel_launch(void* const* d_in, const int* in_sizes, int n_in,
                              void* d_out, int out_size)
{
    const float4* V      = (const float4*)d_in[0];   // [13,2,2048,1024] f32
    const float4* rms_w  = (const float4*)d_in[1];   // [1024] f32
    const float4* w_proj = (const float4*)d_in[2];   // [1024] f32
    float4* out          = (float4*)d_out;           // [2,2048,1024] f32

    cudaFuncSetAttribute(attn_res_block_kernel,
                         cudaFuncAttributeMaxDynamicSharedMemorySize, SMEM_BYTES);

    attn_res_block_kernel<<<GRID, THREADS, SMEM_BYTES>>>(V, rms_w, w_proj, out);
}

// round 17
// speedup vs baseline: 1.0092x; 1.0092x over previous
#include <cuda_runtime.h>
#include <cuda_bf16.h>
#include <math.h>
#include <stdint.h>

// Problem constants
#define NN 13
#define BB 2
#define TT 2048
#define DD 1024
#define ROW_F4 (DD / 4)          // 256 float4 per row
#define NTILES (BB * TT)         // 4096
#define THREADS 544              // 2 consumer gangs x 256 + 1 producer warp
#define GRID 152                 // 1 CTA per SM
#define SLOTS 4                  // gang g owns slots {g, g+2}
#define EPS 1.1920928955078125e-07f   // FLT_EPSILON

#define BUF_F4      (NN * ROW_F4)
#define TILE_BYTES  (BUF_F4 * 16)            // 53248
#define SMEM_BYTES  (SLOTS * TILE_BYTES)     // 212992

__device__ __forceinline__ uint32_t smem_u32(const void* p) {
    uint32_t a;
    asm("{ .reg .u64 t; cvta.to.shared.u64 t, %1; cvt.u32.u64 %0, t; }"
        : "=r"(a) : "l"(p));
    return a;
}
__device__ __forceinline__ void mbar_init(uint32_t m, uint32_t cnt) {
    asm volatile("mbarrier.init.shared.b64 [%0], %1;" :: "r"(m), "r"(cnt) : "memory");
}
__device__ __forceinline__ void mbar_expect_tx(uint32_t m, uint32_t bytes) {
    asm volatile("mbarrier.arrive.expect_tx.shared.b64 _, [%0], %1;"
                 :: "r"(m), "r"(bytes) : "memory");
}
__device__ __forceinline__ void mbar_arrive(uint32_t m) {
    asm volatile("mbarrier.arrive.shared.b64 _, [%0];" :: "r"(m) : "memory");
}
__device__ __forceinline__ void mbar_wait(uint32_t m, uint32_t parity) {
    asm volatile(
        "{\n\t.reg .pred P;\n\t"
        "WAIT_%=:\n\t"
        "mbarrier.try_wait.parity.acquire.cta.shared::cta.b64 P, [%0], %1, 0x989680;\n\t"
        "@P bra DONE_%=;\n\t"
        "bra WAIT_%=;\n\t"
        "DONE_%=:\n\t}"
        :: "r"(m), "r"(parity) : "memory");
}
__device__ __forceinline__ void tma_1d(uint32_t dst, const void* src,
                                       uint32_t bytes, uint32_t mbar) {
    asm volatile(
        "cp.async.bulk.shared::cta.global.mbarrier::complete_tx::bytes [%0], [%1], %2, [%3];"
        :: "r"(dst), "l"(src), "r"(bytes), "r"(mbar) : "memory");
}

__global__ __launch_bounds__(THREADS, 1)
void attn_res_block_kernel(const float4* __restrict__ V,
                           const float4* __restrict__ rms_w,
                           const float4* __restrict__ w_proj,
                           float4* __restrict__ out)
{
    extern __shared__ float4 sbuf[];                  // [SLOTS][NN][ROW_F4]
    __shared__ __align__(8) uint64_t mb_full[SLOTS];  // tx-count completion
    __shared__ __align__(8) uint64_t mb_empty[SLOTS]; // 8 gang-warp arrivals
    __shared__ float s_logit[SLOTS][NN];

    const int tid  = threadIdx.x;
    const int lane = tid & 31;
    const int wid  = tid >> 5;                        // 0..16

    const uint32_t full_a  = smem_u32(&mb_full[0]);
    const uint32_t empty_a = smem_u32(&mb_empty[0]);
    const uint32_t sb_a    = smem_u32(sbuf);

    if (tid == 0) {
        #pragma unroll
        for (int s = 0; s < SLOTS; s++) {
            mbar_init(full_a  + s * 8, 1);
            mbar_init(empty_a + s * 8, 8);    // 8 warps of the owning gang
        }
        asm volatile("fence.proxy.async.shared::cta;" ::: "memory");
    }
    __syncthreads();

    // ================= Producer warp (wid == 16) =================
    if (wid == 16) {
        if (lane == 0) {
            int j = 0;
            for (int t = blockIdx.x; t < NTILES; t += GRID, j++) {
                const int s = j & (SLOTS - 1);
                const int u = j >> 2;                 // fill # for this slot
                if (u >= 1)
                    mbar_wait(empty_a + s * 8, (u - 1) & 1);
                mbar_expect_tx(full_a + s * 8, TILE_BYTES);
                #pragma unroll
                for (int n = 0; n < NN; n++)
                    tma_1d(sb_a + (uint32_t)(s * BUF_F4 + n * ROW_F4) * 16u,
                           (const void*)(V + ((long)n * NTILES + t) * ROW_F4),
                           (uint32_t)(ROW_F4 * 16), full_a + s * 8);
            }
        }
        return;
    }

    // ================= Consumer gangs =================
    // Gang g = warps [8g, 8g+8), 256 threads. Gang g processes tiles with
    // j % 2 == g; slot = j & 3 -> gang 0 owns slots {0,2}, gang 1 owns {1,3}.
    const int gid  = tid >> 8;                        // 0 or 1
    const int ctid = tid & 255;                       // id within gang
    const int cwid = ctid >> 5;                       // 0..7

    // Lane-indexed combined weight (rms_weight * w_proj), registers.
    float4 cw[8];
    #pragma unroll
    for (int k = 0; k < 8; k++) {
        float4 a = rms_w[k * 32 + lane];
        float4 b = w_proj[k * 32 + lane];
        cw[k] = make_float4(a.x * b.x, a.y * b.y, a.z * b.z, a.w * b.w);
    }

    for (int j = gid; ; j += 2) {
        const long tile = (long)blockIdx.x + (long)j * GRID;
        if (tile >= NTILES) break;
        const int s = j & (SLOTS - 1);
        mbar_wait(full_a + s * 8, (j >> 2) & 1);

        const float4* cur = sbuf + s * BUF_F4;

        // ---- Phase 1 (row-mapped): warp cwid owns rows cwid and cwid+8.
        #pragma unroll
        for (int rep = 0; rep < 2; rep++) {
            const int r = cwid + rep * 8;
            if (r < NN) {
                float tss = 0.f, tdp = 0.f;
                #pragma unroll
                for (int k = 0; k < 8; k++) {
                    float4 x = cur[r * ROW_F4 + k * 32 + lane];
                    tss = fmaf(x.x, x.x, fmaf(x.y, x.y, fmaf(x.z, x.z, fmaf(x.w, x.w, tss))));
                    tdp = fmaf(x.x, cw[k].x, fmaf(x.y, cw[k].y, fmaf(x.z, cw[k].z, fmaf(x.w, cw[k].w, tdp))));
                }
                // Split-pair reduction (6 shuffles instead of 10).
                float keep = (lane < 16) ? tss : tdp;
                float give = (lane < 16) ? tdp : tss;
                give = __shfl_xor_sync(0xFFFFFFFFu, give, 16);
                float red = keep + give;
                #pragma unroll
                for (int off = 8; off > 0; off >>= 1)
                    red += __shfl_xor_sync(0xFFFFFFFFu, red, off);
                float dp_tot = __shfl_sync(0xFFFFFFFFu, red, 16);
                if (lane == 0)
                    s_logit[s][r] = rsqrtf(red * (1.0f / DD) + EPS) * dp_tot;
            }
        }
        // Gang-local named barrier (producer + other gang excluded).
        if (gid == 0)
            asm volatile("bar.sync 1, 256;" ::: "memory");
        else
            asm volatile("bar.sync 2, 256;" ::: "memory");

        // ---- Softmax: per-warp redundant; values in lanes 0..12 -> 4 steps.
        float lv = (lane < NN) ? s_logit[s][lane] : -INFINITY;
        float mx = lv;
        #pragma unroll
        for (int off = 8; off > 0; off >>= 1)
            mx = fmaxf(mx, __shfl_xor_sync(0xFFFFFFFFu, mx, off));
        float e = (lane < NN) ? __expf(lv - mx) : 0.f;
        float sm = e;
        #pragma unroll
        for (int off = 8; off > 0; off >>= 1)
            sm += __shfl_xor_sync(0xFFFFFFFFu, sm, off);
        const float av = e * (1.0f / sm);             // alpha for depth = lane

        float a[NN];
        #pragma unroll
        for (int n = 0; n < NN; n++)
            a[n] = __shfl_sync(0xFFFFFFFFu, av, n);

        // ---- Phase 2 (column-mapped): 256 threads x float4 covers the row.
        {
            float4 o = make_float4(0.f, 0.f, 0.f, 0.f);
            #pragma unroll
            for (int n = 0; n < NN; n++) {
                float4 x = cur[n * ROW_F4 + ctid];
                o.x = fmaf(a[n], x.x, o.x);
                o.y = fmaf(a[n], x.y, o.y);
                o.z = fmaf(a[n], x.z, o.z);
                o.w = fmaf(a[n], x.w, o.w);
            }
            out[tile * ROW_F4 + ctid] = o;
        }

        // Slot consumed by this warp (convergent) -> non-blocking arrive.
        if (lane == 0) mbar_arrive(empty_a + s * 8);
    }
}

extern "C" void kernel_launch(void* const* d_in, const int* in_sizes, int n_in,
                              void* d_out, int out_size)
{
    const float4* V      = (const float4*)d_in[0];   // [13,2,2048,1024] f32
    const float4* rms_w  = (const float4*)d_in[1];   // [1024] f32
    const float4* w_proj = (const float4*)d_in[2];   // [1024] f32
    float4* out          = (float4*)d_out;           // [2,2048,1024] f32

    cudaFuncSetAttribute(attn_res_block_kernel,
                         cudaFuncAttributeMaxDynamicSharedMemorySize, SMEM_BYTES);

    attn_res_block_kernel<<<GRID, THREADS, SMEM_BYTES>>>(V, rms_w, w_proj, out);
}